// round 2
// baseline (speedup 1.0000x reference)
#include <cuda_runtime.h>

// Problem constants
#define B_SZ     32
#define C_INPUT  64
#define L_IN     8192
#define L_OUT    8186
#define PF       128

// Tiling
#define T_OUT    128          // output time positions per CTA
#define THREADS  256
#define NX       (T_OUT + 14) // 142 x values per channel (halo -8 .. +6)
#define N1       (T_OUT + 12) // 140 layer-1 positions (halo -8 .. +4)
#define N2       (T_OUT + 8)  // 136 layer-2 positions (halo -8 .. 0)
#define STRIDE   144          // padded SMEM row stride in floats

// SMEM layout (floats)
#define OFF_SX    0
#define OFF_SM1   (OFF_SX  + 64 * STRIDE)   // 9216
#define OFF_SM2   (OFF_SM1 + 18 * STRIDE)   // +2592
#define OFF_SW1   (OFF_SM2 + 12 * STRIDE)   // +1728
#define OFF_SW2   (OFF_SW1 + 18 * 64 * 4)   // +4608
#define OFF_SW7   (OFF_SW2 + 12 * 6 * 4)    // +288
#define OFF_SW10  (OFF_SW7 + 128 * 6 * 4)   // +3072
#define OFF_SW15  (OFF_SW10 + 128 * 6 * 2)  // +1536
#define SMEM_FLOATS (OFF_SW15 + 128 * 6 * 4)
#define SMEM_BYTES  (SMEM_FLOATS * 4)       // 104448 bytes

extern __shared__ float smem[];

__global__ void __launch_bounds__(THREADS, 2) incep_fused_kernel(
    const float* __restrict__ x,
    const float* __restrict__ w7_1,  const float* __restrict__ w7_3,
    const float* __restrict__ w10_1, const float* __restrict__ w10_3, const float* __restrict__ w10_5,
    const float* __restrict__ w15_1, const float* __restrict__ w15_3, const float* __restrict__ w15_5,
    float* __restrict__ out)
{
    float* sx   = smem + OFF_SX;    // [64][144]  x tile (local idx i -> global t0-8+i)
    float* sm1  = smem + OFF_SM1;   // [18][144]  m7a(0-5), m10a(6-11), m15a(12-17)
    float* sm2  = smem + OFF_SM2;   // [12][144]  m10b(0-5), m15b(6-11)
    float* sw1  = smem + OFF_SW1;   // [18][64][4] layer-1 weights, padded
    float* sw2  = smem + OFF_SW2;   // [12][6][4]  layer-2 weights (w10_3, w15_3)
    float* sw7  = smem + OFF_SW7;   // [128][6][4] w7_3
    float* sw10 = smem + OFF_SW10;  // [128][6][2] w10_5 (kw=2, natural layout)
    float* sw15 = smem + OFF_SW15;  // [128][6][4] w15_5

    const int tid = threadIdx.x;
    const int b   = blockIdx.y;
    const int t0  = blockIdx.x * T_OUT;

    // ---- stage weights (padded so each c-iter is one float4/float2 broadcast) ----
    for (int i = tid; i < 18 * 192; i += THREADS) {
        int o = i / 192, r = i % 192, c = r / 3, j = r % 3;
        float v = (o < 6) ? w7_1[i] : (o < 12) ? w10_1[i - 1152] : w15_1[i - 2304];
        sw1[(o * 64 + c) * 4 + j] = v;
    }
    for (int i = tid; i < 12 * 18; i += THREADS) {
        int o = i / 18, r = i % 18, c = r / 3, j = r % 3;
        float v = (o < 6) ? w10_3[i] : w15_3[i - 108];
        sw2[(o * 6 + c) * 4 + j] = v;
    }
    for (int i = tid; i < 128 * 18; i += THREADS) {
        int o = i / 18, r = i % 18, c = r / 3, j = r % 3;
        sw7 [(o * 6 + c) * 4 + j] = w7_3[i];
        sw15[(o * 6 + c) * 4 + j] = w15_5[i];
    }
    for (int i = tid; i < 128 * 12; i += THREADS) sw10[i] = w10_5[i];

    // ---- stage x tile: 64 channels x NX positions, zero-filled out of range ----
    {
        const float* xb = x + (long long)b * C_INPUT * L_IN;
        int warp = tid >> 5, lane = tid & 31;
        for (int c = warp; c < C_INPUT; c += (THREADS / 32)) {
            const float* xc  = xb + (long long)c * L_IN;
            float*       sxc = sx + c * STRIDE;
            for (int i = lane; i < NX; i += 32) {
                int g = t0 - 8 + i;
                sxc[i] = (g >= 0 && g < L_IN) ? xc[g] : 0.0f;
            }
        }
    }
    __syncthreads();

    // ---- layer 1: 18 out-ch x 140 positions (35 blocks of 4), kw=3, d=1 ----
    // m?a[s] = relu(sum_c sum_j w[oc][c][j] * x[c][s+j])
    for (int idx = tid; idx < 18 * 35; idx += THREADS) {
        int oc = idx / 35;
        int p0 = (idx % 35) * 4;
        float a0 = 0.f, a1 = 0.f, a2 = 0.f, a3 = 0.f;
        const float4* wr = (const float4*)(sw1 + oc * 64 * 4);
        #pragma unroll 4
        for (int c = 0; c < 64; c++) {
            const float* xc = sx + c * STRIDE + p0;
            float4 va = *(const float4*)xc;
            float2 vb = *(const float2*)(xc + 4);
            float4 w  = wr[c];
            a0 = fmaf(w.x, va.x, fmaf(w.y, va.y, fmaf(w.z, va.z, a0)));
            a1 = fmaf(w.x, va.y, fmaf(w.y, va.z, fmaf(w.z, va.w, a1)));
            a2 = fmaf(w.x, va.z, fmaf(w.y, va.w, fmaf(w.z, vb.x, a2)));
            a3 = fmaf(w.x, va.w, fmaf(w.y, vb.x, fmaf(w.z, vb.y, a3)));
        }
        float* o = sm1 + oc * STRIDE + p0;
        o[0] = fmaxf(a0, 0.f); o[1] = fmaxf(a1, 0.f);
        o[2] = fmaxf(a2, 0.f); o[3] = fmaxf(a3, 0.f);
    }
    __syncthreads();

    // ---- layer 2: m10b / m15b : 12 out-ch x 136 positions, kw=3, d=2 ----
    // NOTE: positions p<8 correspond to u<0 — the reference's causal padding
    // inserts literal ZEROS there; force them to zero (only t0==0 has p<8 -> u<0).
    for (int idx = tid; idx < 12 * 34; idx += THREADS) {
        int oc = idx / 34;
        int p0 = (idx % 34) * 4;
        int br = oc / 6;                                   // 0 -> m10a, 1 -> m15a
        const float*  min_ = sm1 + (6 + br * 6) * STRIDE;  // input channel base
        const float4* wr   = (const float4*)(sw2 + oc * 6 * 4);
        float a0 = 0.f, a1 = 0.f, a2 = 0.f, a3 = 0.f;
        #pragma unroll
        for (int c = 0; c < 6; c++) {
            const float* mc = min_ + c * STRIDE + p0;
            float4 va = *(const float4*)mc;        // positions p0 .. p0+3
            float4 vb = *(const float4*)(mc + 4);  // positions p0+4 .. p0+7
            float4 w  = wr[c];
            // taps at +0, +2, +4
            a0 = fmaf(w.x, va.x, fmaf(w.y, va.z, fmaf(w.z, vb.x, a0)));
            a1 = fmaf(w.x, va.y, fmaf(w.y, va.w, fmaf(w.z, vb.y, a1)));
            a2 = fmaf(w.x, va.z, fmaf(w.y, vb.x, fmaf(w.z, vb.z, a2)));
            a3 = fmaf(w.x, va.w, fmaf(w.y, vb.y, fmaf(w.z, vb.w, a3)));
        }
        if (t0 == 0 && p0 < 8) { a0 = a1 = a2 = a3 = 0.f; }  // causal pad zeros (u<0)
        float* o = sm2 + oc * STRIDE + p0;
        o[0] = fmaxf(a0, 0.f); o[1] = fmaxf(a1, 0.f);
        o[2] = fmaxf(a2, 0.f); o[3] = fmaxf(a3, 0.f);
    }
    __syncthreads();

    // ---- final layer: 384 out-ch x 128 positions (warp-uniform o, lane = pos-block) ----
    float* outb = out + (long long)b * (3 * PF) * L_OUT;
    for (int idx = tid; idx < 384 * 32; idx += THREADS) {
        int o  = idx >> 5;          // whole warp shares o -> weight broadcast
        int p0 = (idx & 31) * 4;    // lane-consecutive float4 positions
        float a0 = 0.f, a1 = 0.f, a2 = 0.f, a3 = 0.f;
        if (o < 128) {
            // branch 7: m7a (sm1 rows 0-5), taps at local p0+8 + {0,2,4}
            const float4* wr = (const float4*)(sw7 + o * 6 * 4);
            #pragma unroll
            for (int c = 0; c < 6; c++) {
                const float* mc = sm1 + c * STRIDE + p0 + 8;
                float4 va = *(const float4*)mc;
                float4 vb = *(const float4*)(mc + 4);
                float4 w  = wr[c];
                a0 = fmaf(w.x, va.x, fmaf(w.y, va.z, fmaf(w.z, vb.x, a0)));
                a1 = fmaf(w.x, va.y, fmaf(w.y, va.w, fmaf(w.z, vb.y, a1)));
                a2 = fmaf(w.x, va.z, fmaf(w.y, vb.x, fmaf(w.z, vb.z, a2)));
                a3 = fmaf(w.x, va.w, fmaf(w.y, vb.y, fmaf(w.z, vb.w, a3)));
            }
        } else if (o < 256) {
            // branch 10: m10b (sm2 rows 0-5), kw=2 d=4 pad4: taps at p0+4, p0+8
            const float2* wr = (const float2*)(sw10 + (o - 128) * 6 * 2);
            #pragma unroll
            for (int c = 0; c < 6; c++) {
                const float* mc = sm2 + c * STRIDE + p0 + 4;
                float4 va = *(const float4*)mc;
                float4 vb = *(const float4*)(mc + 4);
                float2 w  = wr[c];
                a0 = fmaf(w.x, va.x, fmaf(w.y, vb.x, a0));
                a1 = fmaf(w.x, va.y, fmaf(w.y, vb.y, a1));
                a2 = fmaf(w.x, va.z, fmaf(w.y, vb.z, a2));
                a3 = fmaf(w.x, va.w, fmaf(w.y, vb.w, a3));
            }
        } else {
            // branch 15: m15b (sm2 rows 6-11), kw=3 d=4 pad8: taps at p0, p0+4, p0+8
            const float4* wr = (const float4*)(sw15 + (o - 256) * 6 * 4);
            #pragma unroll
            for (int c = 0; c < 6; c++) {
                const float* mc = sm2 + (6 + c) * STRIDE + p0;
                float4 va = *(const float4*)mc;
                float4 vb = *(const float4*)(mc + 4);
                float4 vc = *(const float4*)(mc + 8);
                float4 w  = wr[c];
                a0 = fmaf(w.x, va.x, fmaf(w.y, vb.x, fmaf(w.z, vc.x, a0)));
                a1 = fmaf(w.x, va.y, fmaf(w.y, vb.y, fmaf(w.z, vc.y, a1)));
                a2 = fmaf(w.x, va.z, fmaf(w.y, vb.z, fmaf(w.z, vc.z, a2)));
                a3 = fmaf(w.x, va.w, fmaf(w.y, vb.w, fmaf(w.z, vc.w, a3)));
            }
        }
        a0 = fmaxf(a0, 0.f); a1 = fmaxf(a1, 0.f);
        a2 = fmaxf(a2, 0.f); a3 = fmaxf(a3, 0.f);

        int t = t0 + p0;
        float* op = outb + (long long)o * L_OUT + t;   // (o*8186 + t) is 2-float aligned
        if (t + 3 < L_OUT) {
            *(float2*)op       = make_float2(a0, a1);
            *(float2*)(op + 2) = make_float2(a2, a3);
        } else {
            if (t     < L_OUT) op[0] = a0;
            if (t + 1 < L_OUT) op[1] = a1;
            if (t + 2 < L_OUT) op[2] = a2;
            if (t + 3 < L_OUT) op[3] = a3;
        }
    }
}

extern "C" void kernel_launch(void* const* d_in, const int* in_sizes, int n_in,
                              void* d_out, int out_size)
{
    const float* x     = (const float*)d_in[0];
    const float* w7_1  = (const float*)d_in[1];
    const float* w7_3  = (const float*)d_in[2];
    const float* w10_1 = (const float*)d_in[3];
    const float* w10_3 = (const float*)d_in[4];
    const float* w10_5 = (const float*)d_in[5];
    const float* w15_1 = (const float*)d_in[6];
    const float* w15_3 = (const float*)d_in[7];
    const float* w15_5 = (const float*)d_in[8];
    float* out = (float*)d_out;

    cudaFuncSetAttribute(incep_fused_kernel,
                         cudaFuncAttributeMaxDynamicSharedMemorySize, SMEM_BYTES);

    dim3 grid((L_OUT + T_OUT - 1) / T_OUT, B_SZ);  // (64, 32)
    incep_fused_kernel<<<grid, THREADS, SMEM_BYTES>>>(
        x, w7_1, w7_3, w10_1, w10_3, w10_5, w15_1, w15_3, w15_5, out);
}

// round 3
// speedup vs baseline: 1.4338x; 1.4338x over previous
#include <cuda_runtime.h>

// Problem constants
#define B_SZ     32
#define C_INPUT  64
#define L_IN     8192
#define L_OUT    8186
#define PF       128

// Tiling
#define T_OUT    128          // output time positions per CTA
#define THREADS  256
#define NX       (T_OUT + 14) // 142 x values per channel (halo -8 .. +6)
#define STRIDE   144          // padded SMEM row stride in floats

// SMEM layout (floats)
#define OFF_SX     0
#define OFF_SM1    (OFF_SX   + 64 * STRIDE)   // 9216
#define OFF_SM2    (OFF_SM1  + 18 * STRIDE)   // 11808
#define OFF_SW1    (OFF_SM2  + 12 * STRIDE)   // 13536
#define OFF_SW2    (OFF_SW1  + 18 * 64 * 4)   // 18144
#define OFF_SW7P   (OFF_SW2  + 12 * 6 * 4)    // 18432
#define OFF_SW10P  (OFF_SW7P + 128 * 20)      // 20992
#define OFF_SW15P  (OFF_SW10P+ 128 * 12)      // 22528
#define SMEM_FLOATS (OFF_SW15P + 128 * 20)    // 25088
#define SMEM_BYTES  (SMEM_FLOATS * 4)         // 100352 bytes

extern __shared__ float smem[];

__device__ __forceinline__ void store4(float* outb, int o, int t,
                                       float a0, float a1, float a2, float a3)
{
    a0 = fmaxf(a0, 0.f); a1 = fmaxf(a1, 0.f);
    a2 = fmaxf(a2, 0.f); a3 = fmaxf(a3, 0.f);
    float* op = outb + (long long)o * L_OUT + t;
    if (t + 3 < L_OUT) {
        *(float2*)op       = make_float2(a0, a1);
        *(float2*)(op + 2) = make_float2(a2, a3);
    } else {
        if (t     < L_OUT) op[0] = a0;
        if (t + 1 < L_OUT) op[1] = a1;
        if (t + 2 < L_OUT) op[2] = a2;
        if (t + 3 < L_OUT) op[3] = a3;
    }
}

__global__ void __launch_bounds__(THREADS, 2) incep_fused_kernel(
    const float* __restrict__ x,
    const float* __restrict__ w7_1,  const float* __restrict__ w7_3,
    const float* __restrict__ w10_1, const float* __restrict__ w10_3, const float* __restrict__ w10_5,
    const float* __restrict__ w15_1, const float* __restrict__ w15_3, const float* __restrict__ w15_5,
    float* __restrict__ out)
{
    float* sx    = smem + OFF_SX;     // [64][144]  x tile (local i -> global t0-8+i)
    float* sm1   = smem + OFF_SM1;    // [18][144]  m7a(0-5), m10a(6-11), m15a(12-17)
    float* sm2   = smem + OFF_SM2;    // [12][144]  m10b(0-5), m15b(6-11)
    float* sw1   = smem + OFF_SW1;    // [18][64][4] layer-1 weights, tap-padded
    float* sw2   = smem + OFF_SW2;    // [12][6][4]  layer-2 weights
    float* sw7p  = smem + OFF_SW7P;   // [128][20]  w7_3 packed (18 + 2 pad)
    float* sw10p = smem + OFF_SW10P;  // [128][12]  w10_5 natural
    float* sw15p = smem + OFF_SW15P;  // [128][20]  w15_5 packed

    const int tid = threadIdx.x;
    const int b   = blockIdx.y;
    const int t0  = blockIdx.x * T_OUT;

    // ---- stage weights ----
    for (int i = tid; i < 18 * 192; i += THREADS) {
        int o = i / 192, r = i % 192, c = r / 3, j = r % 3;
        float v = (o < 6) ? w7_1[i] : (o < 12) ? w10_1[i - 1152] : w15_1[i - 2304];
        sw1[(o * 64 + c) * 4 + j] = v;
    }
    for (int i = tid; i < 12 * 18; i += THREADS) {
        int o = i / 18, r = i % 18, c = r / 3, j = r % 3;
        float v = (o < 6) ? w10_3[i] : w15_3[i - 108];
        sw2[(o * 6 + c) * 4 + j] = v;
    }
    for (int i = tid; i < 128 * 18; i += THREADS) {
        int o = i / 18, r = i % 18;
        sw7p [o * 20 + r] = w7_3[i];
        sw15p[o * 20 + r] = w15_5[i];
    }
    if (tid < 128) {
        sw7p [tid * 20 + 18] = 0.f; sw7p [tid * 20 + 19] = 0.f;
        sw15p[tid * 20 + 18] = 0.f; sw15p[tid * 20 + 19] = 0.f;
    }
    for (int i = tid; i < 128 * 12; i += THREADS) sw10p[i] = w10_5[i];

    // ---- stage x tile ----
    {
        const float* xb = x + (long long)b * C_INPUT * L_IN;
        int warp = tid >> 5, lane = tid & 31;
        for (int c = warp; c < C_INPUT; c += (THREADS / 32)) {
            const float* xc  = xb + (long long)c * L_IN;
            float*       sxc = sx + c * STRIDE;
            for (int i = lane; i < NX; i += 32) {
                int g = t0 - 8 + i;
                sxc[i] = (g >= 0 && g < L_IN) ? xc[g] : 0.0f;
            }
        }
    }
    __syncthreads();

    // ---- layer 1: thread = (oc-group of 3, pos-block of 4). 210 threads. ----
    if (tid < 210) {
        int ocg = tid / 35, pb = tid % 35, p0 = pb * 4;
        int oc0 = ocg * 3;
        float acc[3][4] = {{0.f,0.f,0.f,0.f},{0.f,0.f,0.f,0.f},{0.f,0.f,0.f,0.f}};
        const float4* w0r = (const float4*)(sw1 + (oc0 + 0) * 256);
        const float4* w1r = (const float4*)(sw1 + (oc0 + 1) * 256);
        const float4* w2r = (const float4*)(sw1 + (oc0 + 2) * 256);
        #pragma unroll 4
        for (int c = 0; c < 64; c++) {
            const float* xc = sx + c * STRIDE + p0;
            float4 va = *(const float4*)xc;
            float2 vb = *(const float2*)(xc + 4);
            float d0 = va.x, d1 = va.y, d2 = va.z, d3 = va.w, d4 = vb.x, d5 = vb.y;
            float4 w;
            w = w0r[c];
            acc[0][0] = fmaf(w.x,d0,fmaf(w.y,d1,fmaf(w.z,d2,acc[0][0])));
            acc[0][1] = fmaf(w.x,d1,fmaf(w.y,d2,fmaf(w.z,d3,acc[0][1])));
            acc[0][2] = fmaf(w.x,d2,fmaf(w.y,d3,fmaf(w.z,d4,acc[0][2])));
            acc[0][3] = fmaf(w.x,d3,fmaf(w.y,d4,fmaf(w.z,d5,acc[0][3])));
            w = w1r[c];
            acc[1][0] = fmaf(w.x,d0,fmaf(w.y,d1,fmaf(w.z,d2,acc[1][0])));
            acc[1][1] = fmaf(w.x,d1,fmaf(w.y,d2,fmaf(w.z,d3,acc[1][1])));
            acc[1][2] = fmaf(w.x,d2,fmaf(w.y,d3,fmaf(w.z,d4,acc[1][2])));
            acc[1][3] = fmaf(w.x,d3,fmaf(w.y,d4,fmaf(w.z,d5,acc[1][3])));
            w = w2r[c];
            acc[2][0] = fmaf(w.x,d0,fmaf(w.y,d1,fmaf(w.z,d2,acc[2][0])));
            acc[2][1] = fmaf(w.x,d1,fmaf(w.y,d2,fmaf(w.z,d3,acc[2][1])));
            acc[2][2] = fmaf(w.x,d2,fmaf(w.y,d3,fmaf(w.z,d4,acc[2][2])));
            acc[2][3] = fmaf(w.x,d3,fmaf(w.y,d4,fmaf(w.z,d5,acc[2][3])));
        }
        #pragma unroll
        for (int r = 0; r < 3; r++) {
            float* o = sm1 + (oc0 + r) * STRIDE + p0;
            o[0] = fmaxf(acc[r][0], 0.f); o[1] = fmaxf(acc[r][1], 0.f);
            o[2] = fmaxf(acc[r][2], 0.f); o[3] = fmaxf(acc[r][3], 0.f);
        }
    }
    __syncthreads();

    // ---- layer 2: 12 oc x 136 positions, kw=3, d=2.  Causal zeros for u<0. ----
    for (int idx = tid; idx < 12 * 34; idx += THREADS) {
        int oc = idx / 34;
        int p0 = (idx % 34) * 4;
        int br = oc / 6;
        const float*  min_ = sm1 + (6 + br * 6) * STRIDE;
        const float4* wr   = (const float4*)(sw2 + oc * 6 * 4);
        float a0 = 0.f, a1 = 0.f, a2 = 0.f, a3 = 0.f;
        #pragma unroll
        for (int c = 0; c < 6; c++) {
            const float* mc = min_ + c * STRIDE + p0;
            float4 va = *(const float4*)mc;
            float4 vb = *(const float4*)(mc + 4);
            float4 w  = wr[c];
            a0 = fmaf(w.x, va.x, fmaf(w.y, va.z, fmaf(w.z, vb.x, a0)));
            a1 = fmaf(w.x, va.y, fmaf(w.y, va.w, fmaf(w.z, vb.y, a1)));
            a2 = fmaf(w.x, va.z, fmaf(w.y, vb.x, fmaf(w.z, vb.z, a2)));
            a3 = fmaf(w.x, va.w, fmaf(w.y, vb.y, fmaf(w.z, vb.w, a3)));
        }
        if (t0 == 0 && p0 < 8) { a0 = a1 = a2 = a3 = 0.f; }   // causal padding zeros
        float* o = sm2 + oc * STRIDE + p0;
        o[0] = fmaxf(a0, 0.f); o[1] = fmaxf(a1, 0.f);
        o[2] = fmaxf(a2, 0.f); o[3] = fmaxf(a3, 0.f);
    }
    __syncthreads();

    // ---- final layer: warp g owns ocs [16g,16g+16); lane = 4-pos block.        ----
    // ---- Data loaded ONCE per thread into registers; weights are broadcasts.   ----
    const int g    = tid >> 5;
    const int lane = tid & 31;
    const int p0   = lane * 4;
    const int t    = t0 + p0;
    float* outb = out + (long long)b * (3 * PF) * L_OUT;

    // ----- branch 7: in = sm1 rows 0-5 at p0+8..p0+15, taps {0,2,4} -----
    {
        float d[6][8];
        #pragma unroll
        for (int c = 0; c < 6; c++) {
            const float* mc = sm1 + c * STRIDE + p0 + 8;
            float4 lo = *(const float4*)mc;
            float4 hi = *(const float4*)(mc + 4);
            d[c][0]=lo.x; d[c][1]=lo.y; d[c][2]=lo.z; d[c][3]=lo.w;
            d[c][4]=hi.x; d[c][5]=hi.y; d[c][6]=hi.z; d[c][7]=hi.w;
        }
        #pragma unroll 2
        for (int k = 0; k < 16; k++) {
            int o = g * 16 + k;
            const float4* q = (const float4*)(sw7p + o * 20);
            float4 q0=q[0], q1=q[1], q2=q[2], q3=q[3], q4=q[4];
            float wt[18] = {q0.x,q0.y,q0.z,q0.w,q1.x,q1.y,q1.z,q1.w,
                            q2.x,q2.y,q2.z,q2.w,q3.x,q3.y,q3.z,q3.w,q4.x,q4.y};
            float a0=0.f,a1=0.f,a2=0.f,a3=0.f;
            #pragma unroll
            for (int c = 0; c < 6; c++) {
                float w0=wt[c*3], w1=wt[c*3+1], w2=wt[c*3+2];
                a0 = fmaf(w0,d[c][0],fmaf(w1,d[c][2],fmaf(w2,d[c][4],a0)));
                a1 = fmaf(w0,d[c][1],fmaf(w1,d[c][3],fmaf(w2,d[c][5],a1)));
                a2 = fmaf(w0,d[c][2],fmaf(w1,d[c][4],fmaf(w2,d[c][6],a2)));
                a3 = fmaf(w0,d[c][3],fmaf(w1,d[c][5],fmaf(w2,d[c][7],a3)));
            }
            store4(outb, o, t, a0, a1, a2, a3);
        }
    }

    // ----- branch 10: in = sm2 rows 0-5 at p0+4..p0+11, taps {0,4} -----
    {
        float d[6][8];
        #pragma unroll
        for (int c = 0; c < 6; c++) {
            const float* mc = sm2 + c * STRIDE + p0 + 4;
            float4 lo = *(const float4*)mc;
            float4 hi = *(const float4*)(mc + 4);
            d[c][0]=lo.x; d[c][1]=lo.y; d[c][2]=lo.z; d[c][3]=lo.w;
            d[c][4]=hi.x; d[c][5]=hi.y; d[c][6]=hi.z; d[c][7]=hi.w;
        }
        #pragma unroll 2
        for (int k = 0; k < 16; k++) {
            int o = g * 16 + k;
            const float4* q = (const float4*)(sw10p + o * 12);
            float4 q0=q[0], q1=q[1], q2=q[2];
            float wt[12] = {q0.x,q0.y,q0.z,q0.w,q1.x,q1.y,q1.z,q1.w,
                            q2.x,q2.y,q2.z,q2.w};
            float a0=0.f,a1=0.f,a2=0.f,a3=0.f;
            #pragma unroll
            for (int c = 0; c < 6; c++) {
                float w0=wt[c*2], w1=wt[c*2+1];
                a0 = fmaf(w0,d[c][0],fmaf(w1,d[c][4],a0));
                a1 = fmaf(w0,d[c][1],fmaf(w1,d[c][5],a1));
                a2 = fmaf(w0,d[c][2],fmaf(w1,d[c][6],a2));
                a3 = fmaf(w0,d[c][3],fmaf(w1,d[c][7],a3));
            }
            store4(outb, 128 + o, t, a0, a1, a2, a3);
        }
    }

    // ----- branch 15: in = sm2 rows 6-11 at p0..p0+11, taps {0,4,8} -----
    {
        float d[6][12];
        #pragma unroll
        for (int c = 0; c < 6; c++) {
            const float* mc = sm2 + (6 + c) * STRIDE + p0;
            float4 lo = *(const float4*)mc;
            float4 mi = *(const float4*)(mc + 4);
            float4 hi = *(const float4*)(mc + 8);
            d[c][0]=lo.x; d[c][1]=lo.y; d[c][2] =lo.z; d[c][3] =lo.w;
            d[c][4]=mi.x; d[c][5]=mi.y; d[c][6] =mi.z; d[c][7] =mi.w;
            d[c][8]=hi.x; d[c][9]=hi.y; d[c][10]=hi.z; d[c][11]=hi.w;
        }
        #pragma unroll 1
        for (int k = 0; k < 16; k++) {
            int o = g * 16 + k;
            const float4* q = (const float4*)(sw15p + o * 20);
            float4 q0=q[0], q1=q[1], q2=q[2], q3=q[3], q4=q[4];
            float wt[18] = {q0.x,q0.y,q0.z,q0.w,q1.x,q1.y,q1.z,q1.w,
                            q2.x,q2.y,q2.z,q2.w,q3.x,q3.y,q3.z,q3.w,q4.x,q4.y};
            float a0=0.f,a1=0.f,a2=0.f,a3=0.f;
            #pragma unroll
            for (int c = 0; c < 6; c++) {
                float w0=wt[c*3], w1=wt[c*3+1], w2=wt[c*3+2];
                a0 = fmaf(w0,d[c][0],fmaf(w1,d[c][4],fmaf(w2,d[c][8], a0)));
                a1 = fmaf(w0,d[c][1],fmaf(w1,d[c][5],fmaf(w2,d[c][9], a1)));
                a2 = fmaf(w0,d[c][2],fmaf(w1,d[c][6],fmaf(w2,d[c][10],a2)));
                a3 = fmaf(w0,d[c][3],fmaf(w1,d[c][7],fmaf(w2,d[c][11],a3)));
            }
            store4(outb, 256 + o, t, a0, a1, a2, a3);
        }
    }
}

extern "C" void kernel_launch(void* const* d_in, const int* in_sizes, int n_in,
                              void* d_out, int out_size)
{
    const float* x     = (const float*)d_in[0];
    const float* w7_1  = (const float*)d_in[1];
    const float* w7_3  = (const float*)d_in[2];
    const float* w10_1 = (const float*)d_in[3];
    const float* w10_3 = (const float*)d_in[4];
    const float* w10_5 = (const float*)d_in[5];
    const float* w15_1 = (const float*)d_in[6];
    const float* w15_3 = (const float*)d_in[7];
    const float* w15_5 = (const float*)d_in[8];
    float* out = (float*)d_out;

    cudaFuncSetAttribute(incep_fused_kernel,
                         cudaFuncAttributeMaxDynamicSharedMemorySize, SMEM_BYTES);

    dim3 grid((L_OUT + T_OUT - 1) / T_OUT, B_SZ);  // (64, 32)
    incep_fused_kernel<<<grid, THREADS, SMEM_BYTES>>>(
        x, w7_1, w7_3, w10_1, w10_3, w10_5, w15_1, w15_3, w15_5, out);
}

// round 4
// speedup vs baseline: 1.5983x; 1.1147x over previous
#include <cuda_runtime.h>

// Problem constants
#define B_SZ     32
#define C_INPUT  64
#define L_IN     8192
#define L_OUT    8186
#define PF       128

// Tiling
#define T_OUT    128
#define THREADS  256
#define NX       (T_OUT + 14) // 142 x values per channel (halo -8 .. +6)
#define SXST     142          // x row stride (floats)
#define ST       144          // sm1/sm2 row stride (floats, 16B-aligned rows)

// SMEM layout (floats)
#define OFF_SX     0
#define OFF_SM1    (OFF_SX   + 64 * SXST)      // 9088
#define OFF_SM2    (OFF_SM1  + 18 * ST)        // 11680
#define OFF_SW1I   (OFF_SM2  + 12 * ST)        // 13408  [9 ocpair][64 c][3 tap][2]
#define OFF_SW2    (OFF_SW1I + 9 * 64 * 6)     // 16864  [12][6][4]
#define OFF_SW7D   (OFF_SW2  + 12 * 6 * 4)     // 17152  [128][18][2] duplicated
#define OFF_SW10   (OFF_SW7D + 128 * 36)       // 21760  [128][12] natural
#define OFF_SW15D  (OFF_SW10 + 128 * 12)       // 23296  [128][18][2] duplicated
#define SMEM_FLOATS (OFF_SW15D + 128 * 36)     // 27904
#define SMEM_BYTES  (SMEM_FLOATS * 4)          // 111616 bytes -> 2 CTAs/SM

typedef unsigned long long u64;

__device__ __forceinline__ u64 pk2(float lo, float hi) {
    u64 r; asm("mov.b64 %0, {%1, %2};" : "=l"(r) : "f"(lo), "f"(hi)); return r;
}
__device__ __forceinline__ u64 dup2(float v) { return pk2(v, v); }
__device__ __forceinline__ void fma2(u64& d, u64 a, u64 b) {
    asm("fma.rn.f32x2 %0, %1, %2, %0;" : "+l"(d) : "l"(a), "l"(b));
}
__device__ __forceinline__ float2 up2(u64 v) {
    float lo, hi; asm("mov.b64 {%0, %1}, %2;" : "=f"(lo), "=f"(hi) : "l"(v));
    return make_float2(lo, hi);
}

extern __shared__ float smem[];

__device__ __forceinline__ void store4p(float* outb, int o, int t, u64 A01, u64 A23)
{
    float2 v0 = up2(A01), v1 = up2(A23);
    float a0 = fmaxf(v0.x, 0.f), a1 = fmaxf(v0.y, 0.f);
    float a2 = fmaxf(v1.x, 0.f), a3 = fmaxf(v1.y, 0.f);
    float* op = outb + (long long)o * L_OUT + t;
    if (t + 3 < L_OUT) {
        *(float2*)op       = make_float2(a0, a1);
        *(float2*)(op + 2) = make_float2(a2, a3);
    } else {
        if (t     < L_OUT) op[0] = a0;
        if (t + 1 < L_OUT) op[1] = a1;
        if (t + 2 < L_OUT) op[2] = a2;
        if (t + 3 < L_OUT) op[3] = a3;
    }
}

__global__ void __launch_bounds__(THREADS, 2) incep_fused_kernel(
    const float* __restrict__ x,
    const float* __restrict__ w7_1,  const float* __restrict__ w7_3,
    const float* __restrict__ w10_1, const float* __restrict__ w10_3, const float* __restrict__ w10_5,
    const float* __restrict__ w15_1, const float* __restrict__ w15_3, const float* __restrict__ w15_5,
    float* __restrict__ out)
{
    float* sx    = smem + OFF_SX;    // [64][142]
    float* sm1   = smem + OFF_SM1;   // [18][144] m7a(0-5), m10a(6-11), m15a(12-17)
    float* sm2   = smem + OFF_SM2;   // [12][144] m10b(0-5), m15b(6-11)
    float* sw1i  = smem + OFF_SW1I;  // [9][64][3][2] oc-pair interleaved
    float* sw2   = smem + OFF_SW2;   // [12][6][4]
    float* sw7d  = smem + OFF_SW7D;  // [128][18][2] duplicated pairs
    float* sw10  = smem + OFF_SW10;  // [128][12]
    float* sw15d = smem + OFF_SW15D; // [128][18][2] duplicated pairs

    const int tid = threadIdx.x;
    const int b   = blockIdx.y;
    const int t0  = blockIdx.x * T_OUT;

    // ---- stage weights ----
    // layer 1, oc-pair interleaved: sw1i[q][c][j][s] = w_{2q+s}[c*3+j]
    for (int i = tid; i < 18 * 192; i += THREADS) {
        int o = i / 192, r = i % 192;          // r = c*3+j
        float v = (o < 6) ? w7_1[i] : (o < 12) ? w10_1[i - 1152] : w15_1[i - 2304];
        int q = o >> 1, s = o & 1;
        sw1i[(q * 192 + r) * 2 + s] = v;
    }
    for (int i = tid; i < 12 * 18; i += THREADS) {
        int o = i / 18, r = i % 18, c = r / 3, j = r % 3;
        float v = (o < 6) ? w10_3[i] : w15_3[i - 108];
        sw2[(o * 6 + c) * 4 + j] = v;
    }
    for (int i = tid; i < 128 * 18; i += THREADS) {
        int o = i / 18, r = i % 18;
        float v7 = w7_3[i], v15 = w15_5[i];
        sw7d [o * 36 + r * 2 + 0] = v7;  sw7d [o * 36 + r * 2 + 1] = v7;
        sw15d[o * 36 + r * 2 + 0] = v15; sw15d[o * 36 + r * 2 + 1] = v15;
    }
    for (int i = tid; i < 128 * 12; i += THREADS) sw10[i] = w10_5[i];

    // ---- stage x tile ----
    {
        const float* xb = x + (long long)b * C_INPUT * L_IN;
        int warp = tid >> 5, lane = tid & 31;
        for (int c = warp; c < C_INPUT; c += (THREADS / 32)) {
            const float* xc  = xb + (long long)c * L_IN;
            float*       sxc = sx + c * SXST;
            for (int i = lane; i < NX; i += 32) {
                int g = t0 - 8 + i;
                sxc[i] = (g >= 0 && g < L_IN) ? xc[g] : 0.0f;
            }
        }
    }
    __syncthreads();

    // ---- layer 1 (f32x2 over oc-pairs): 9 ocpairs x 28 five-pos blocks = 252 items
    if (tid < 252) {
        int q  = tid / 28;
        int p0 = (tid % 28) * 5;
        u64 A0 = 0, A1 = 0, A2 = 0, A3 = 0, A4 = 0;
        const float* wrow = sw1i + q * 384;    // 64*6 floats
        #pragma unroll 4
        for (int c = 0; c < 64; c++) {
            const float* xc = sx + c * SXST + p0;
            u64 D0 = dup2(xc[0]), D1 = dup2(xc[1]), D2 = dup2(xc[2]),
                D3 = dup2(xc[3]), D4 = dup2(xc[4]), D5 = dup2(xc[5]), D6 = dup2(xc[6]);
            const float* wc = wrow + c * 6;
            u64 W0 = *(const u64*)(wc + 0);
            u64 W1 = *(const u64*)(wc + 2);
            u64 W2 = *(const u64*)(wc + 4);
            fma2(A0, W0, D0); fma2(A0, W1, D1); fma2(A0, W2, D2);
            fma2(A1, W0, D1); fma2(A1, W1, D2); fma2(A1, W2, D3);
            fma2(A2, W0, D2); fma2(A2, W1, D3); fma2(A2, W2, D4);
            fma2(A3, W0, D3); fma2(A3, W1, D4); fma2(A3, W2, D5);
            fma2(A4, W0, D4); fma2(A4, W1, D5); fma2(A4, W2, D6);
        }
        float* r0 = sm1 + (2 * q)     * ST + p0;
        float* r1 = sm1 + (2 * q + 1) * ST + p0;
        float2 v;
        v = up2(A0); r0[0] = fmaxf(v.x, 0.f); r1[0] = fmaxf(v.y, 0.f);
        v = up2(A1); r0[1] = fmaxf(v.x, 0.f); r1[1] = fmaxf(v.y, 0.f);
        v = up2(A2); r0[2] = fmaxf(v.x, 0.f); r1[2] = fmaxf(v.y, 0.f);
        v = up2(A3); r0[3] = fmaxf(v.x, 0.f); r1[3] = fmaxf(v.y, 0.f);
        v = up2(A4); r0[4] = fmaxf(v.x, 0.f); r1[4] = fmaxf(v.y, 0.f);
    }
    __syncthreads();

    // ---- layer 2: 12 oc x 136 positions, kw=3, d=2. Causal zeros for u<0. ----
    for (int idx = tid; idx < 12 * 34; idx += THREADS) {
        int oc = idx / 34;
        int p0 = (idx % 34) * 4;
        int br = oc / 6;
        const float*  min_ = sm1 + (6 + br * 6) * ST;
        const float4* wr   = (const float4*)(sw2 + oc * 6 * 4);
        float a0 = 0.f, a1 = 0.f, a2 = 0.f, a3 = 0.f;
        #pragma unroll
        for (int c = 0; c < 6; c++) {
            const float* mc = min_ + c * ST + p0;
            float4 va = *(const float4*)mc;
            float4 vb = *(const float4*)(mc + 4);
            float4 w  = wr[c];
            a0 = fmaf(w.x, va.x, fmaf(w.y, va.z, fmaf(w.z, vb.x, a0)));
            a1 = fmaf(w.x, va.y, fmaf(w.y, va.w, fmaf(w.z, vb.y, a1)));
            a2 = fmaf(w.x, va.z, fmaf(w.y, vb.x, fmaf(w.z, vb.z, a2)));
            a3 = fmaf(w.x, va.w, fmaf(w.y, vb.y, fmaf(w.z, vb.w, a3)));
        }
        if (t0 == 0 && p0 < 8) { a0 = a1 = a2 = a3 = 0.f; }   // causal padding zeros
        float* o = sm2 + oc * ST + p0;
        o[0] = fmaxf(a0, 0.f); o[1] = fmaxf(a1, 0.f);
        o[2] = fmaxf(a2, 0.f); o[3] = fmaxf(a3, 0.f);
    }
    __syncthreads();

    // ---- final layer: warp g owns ocs [16g,16g+16); lane = 4-pos block ----
    const int g    = tid >> 5;
    const int lane = tid & 31;
    const int p0   = lane * 4;
    const int t    = t0 + p0;
    float* outb = out + (long long)b * (3 * PF) * L_OUT;

    // ----- branch 7: sm1 rows 0-5 at p0+8..p0+15, taps {0,2,4} -----
    {
        u64 P[6][4];   // P[c][k] = (d_{2k}, d_{2k+1})
        #pragma unroll
        for (int c = 0; c < 6; c++) {
            const ulonglong2* mc = (const ulonglong2*)(sm1 + c * ST + p0 + 8);
            ulonglong2 lo = mc[0], hi = mc[1];
            P[c][0] = lo.x; P[c][1] = lo.y; P[c][2] = hi.x; P[c][3] = hi.y;
        }
        #pragma unroll 1
        for (int k = 0; k < 16; k++) {
            int o = g * 16 + k;
            const ulonglong2* q = (const ulonglong2*)(sw7d + o * 36);
            u64 A01 = 0, A23 = 0;
            #pragma unroll
            for (int c = 0; c < 6; c++) {
                ulonglong2 qa = q[c * 3 / 2 + (c * 3) % 2 * 0];  // placeholder (replaced below)
                (void)qa;
                // weights: 18 dup-pairs per oc, 3 per channel at index c*3..c*3+2
                u64 W0 = ((const u64*)q)[c * 3 + 0];
                u64 W1 = ((const u64*)q)[c * 3 + 1];
                u64 W2 = ((const u64*)q)[c * 3 + 2];
                fma2(A01, W0, P[c][0]); fma2(A01, W1, P[c][1]); fma2(A01, W2, P[c][2]);
                fma2(A23, W0, P[c][1]); fma2(A23, W1, P[c][2]); fma2(A23, W2, P[c][3]);
            }
            store4p(outb, o, t, A01, A23);
        }
    }

    // ----- branch 10: sm2 rows 0-5 at p0+4..p0+11, taps {0,4} -----
    {
        u64 P[6][4];
        #pragma unroll
        for (int c = 0; c < 6; c++) {
            const ulonglong2* mc = (const ulonglong2*)(sm2 + c * ST + p0 + 4);
            ulonglong2 lo = mc[0], hi = mc[1];
            P[c][0] = lo.x; P[c][1] = lo.y; P[c][2] = hi.x; P[c][3] = hi.y;
        }
        #pragma unroll 2
        for (int k = 0; k < 16; k++) {
            int o = g * 16 + k;
            const float4* qw = (const float4*)(sw10 + o * 12);
            float4 q0 = qw[0], q1 = qw[1], q2 = qw[2];
            u64 W[12];
            W[0]=dup2(q0.x); W[1]=dup2(q0.y); W[2] =dup2(q0.z); W[3] =dup2(q0.w);
            W[4]=dup2(q1.x); W[5]=dup2(q1.y); W[6] =dup2(q1.z); W[7] =dup2(q1.w);
            W[8]=dup2(q2.x); W[9]=dup2(q2.y); W[10]=dup2(q2.z); W[11]=dup2(q2.w);
            u64 A01 = 0, A23 = 0;
            #pragma unroll
            for (int c = 0; c < 6; c++) {
                fma2(A01, W[c*2+0], P[c][0]); fma2(A01, W[c*2+1], P[c][2]);
                fma2(A23, W[c*2+0], P[c][1]); fma2(A23, W[c*2+1], P[c][3]);
            }
            store4p(outb, 128 + o, t, A01, A23);
        }
    }

    // ----- branch 15: sm2 rows 6-11 at p0..p0+11, taps {0,4,8} -----
    {
        u64 P[6][6];
        #pragma unroll
        for (int c = 0; c < 6; c++) {
            const ulonglong2* mc = (const ulonglong2*)(sm2 + (6 + c) * ST + p0);
            ulonglong2 lo = mc[0], mi = mc[1], hi = mc[2];
            P[c][0] = lo.x; P[c][1] = lo.y; P[c][2] = mi.x;
            P[c][3] = mi.y; P[c][4] = hi.x; P[c][5] = hi.y;
        }
        #pragma unroll 1
        for (int k = 0; k < 16; k++) {
            int o = g * 16 + k;
            const u64* q = (const u64*)(sw15d + o * 36);
            u64 A01 = 0, A23 = 0;
            #pragma unroll
            for (int c = 0; c < 6; c++) {
                u64 W0 = q[c * 3 + 0];
                u64 W1 = q[c * 3 + 1];
                u64 W2 = q[c * 3 + 2];
                fma2(A01, W0, P[c][0]); fma2(A01, W1, P[c][2]); fma2(A01, W2, P[c][4]);
                fma2(A23, W0, P[c][1]); fma2(A23, W1, P[c][3]); fma2(A23, W2, P[c][5]);
            }
            store4p(outb, 256 + o, t, A01, A23);
        }
    }
}

extern "C" void kernel_launch(void* const* d_in, const int* in_sizes, int n_in,
                              void* d_out, int out_size)
{
    const float* x     = (const float*)d_in[0];
    const float* w7_1  = (const float*)d_in[1];
    const float* w7_3  = (const float*)d_in[2];
    const float* w10_1 = (const float*)d_in[3];
    const float* w10_3 = (const float*)d_in[4];
    const float* w10_5 = (const float*)d_in[5];
    const float* w15_1 = (const float*)d_in[6];
    const float* w15_3 = (const float*)d_in[7];
    const float* w15_5 = (const float*)d_in[8];
    float* out = (float*)d_out;

    cudaFuncSetAttribute(incep_fused_kernel,
                         cudaFuncAttributeMaxDynamicSharedMemorySize, SMEM_BYTES);

    dim3 grid((L_OUT + T_OUT - 1) / T_OUT, B_SZ);  // (64, 32)
    incep_fused_kernel<<<grid, THREADS, SMEM_BYTES>>>(
        x, w7_1, w7_3, w10_1, w10_3, w10_5, w15_1, w15_3, w15_5, out);
}